// round 1
// baseline (speedup 1.0000x reference)
#include <cuda_runtime.h>

// HybridLoss: smooth_l1(preds,targets) + 0.5*(1 - mean(box_overlap))
// preds, targets: [2000000, 10] float32 row-major. Output: 1 float scalar.

#define NROWS 2000000
#define THREADS 256
#define ROWS_PER_BLOCK 256
#define NBLOCKS ((NROWS + ROWS_PER_BLOCK - 1) / ROWS_PER_BLOCK)  // 7813
#define EPSF 1e-6f

__device__ double g_acc[2];   // [0] = sum of smooth-l1 terms, [1] = sum of overlaps

__global__ void hl_init_kernel() {
    g_acc[0] = 0.0;
    g_acc[1] = 0.0;
}

__global__ __launch_bounds__(THREADS) void hl_main_kernel(
    const float* __restrict__ preds,
    const float* __restrict__ targets)
{
    __shared__ float sp[ROWS_PER_BLOCK * 10];
    __shared__ float st[ROWS_PER_BLOCK * 10];

    const int tid  = threadIdx.x;
    const int base = blockIdx.x * ROWS_PER_BLOCK;

    // ---- Stage this block's rows via coalesced float4 loads ----
    // base*10 floats offset -> base*40 bytes; base multiple of 256 so 16B aligned.
    const long base4   = (long)base * 10 / 4;          // float4 offset
    const long total4  = (long)NROWS * 10 / 4;         // 5,000,000
    const float4* __restrict__ p4 = reinterpret_cast<const float4*>(preds)   + base4;
    const float4* __restrict__ t4 = reinterpret_cast<const float4*>(targets) + base4;
    float4* sp4 = reinterpret_cast<float4*>(sp);
    float4* st4 = reinterpret_cast<float4*>(st);

    #pragma unroll
    for (int k = 0; k < 3; k++) {
        int i4 = tid + k * THREADS;                    // up to 640 float4 per array
        if (i4 < (ROWS_PER_BLOCK * 10 / 4) && (base4 + i4) < total4) {
            sp4[i4] = p4[i4];
            st4[i4] = t4[i4];
        }
    }
    __syncthreads();

    float l1_sum = 0.0f;   // sum over the 10 smooth-l1 terms of this row
    float ov     = 0.0f;   // overlap of this row

    const int row = base + tid;
    if (row < NROWS) {
        float p[10], t[10];
        #pragma unroll
        for (int j = 0; j < 10; j++) {
            p[j] = sp[tid * 10 + j];
            t[j] = st[tid * 10 + j];
        }

        // ---- smooth L1 ----
        #pragma unroll
        for (int j = 0; j < 10; j++) {
            float d  = p[j] - t[j];
            float ad = fabsf(d);
            l1_sum += (ad < 1.0f) ? 0.5f * d * d : ad - 0.5f;
        }

        // ---- quaternions -> rotation matrices ----
        float px = p[6], py = p[7], pz = p[8], pw = p[9];
        float gx = t[6], gy = t[7], gz = t[8], gw = t[9];
        float pin = 1.0f / sqrtf(px*px + py*py + pz*pz + pw*pw);
        float gin = 1.0f / sqrtf(gx*gx + gy*gy + gz*gz + gw*gw);
        px *= pin; py *= pin; pz *= pin; pw *= pin;
        gx *= gin; gy *= gin; gz *= gin; gw *= gin;

        float pr[9], gr[9];
        pr[0] = 1.0f - 2.0f*(py*py + pz*pz);
        pr[1] = 2.0f*(px*py + pz*pw);
        pr[2] = 2.0f*(px*pz - py*pw);
        pr[3] = 2.0f*(px*py - pz*pw);
        pr[4] = 1.0f - 2.0f*(px*px + pz*pz);
        pr[5] = 2.0f*(py*pz + px*pw);
        pr[6] = 2.0f*(px*pz + py*pw);
        pr[7] = 2.0f*(py*pz - px*pw);
        pr[8] = 1.0f - 2.0f*(px*px + py*py);

        gr[0] = 1.0f - 2.0f*(gy*gy + gz*gz);
        gr[1] = 2.0f*(gx*gy + gz*gw);
        gr[2] = 2.0f*(gx*gz - gy*gw);
        gr[3] = 2.0f*(gx*gy - gz*gw);
        gr[4] = 1.0f - 2.0f*(gx*gx + gz*gz);
        gr[5] = 2.0f*(gy*gz + gx*gw);
        gr[6] = 2.0f*(gx*gz + gy*gw);
        gr[7] = 2.0f*(gy*gz - gx*gw);
        gr[8] = 1.0f - 2.0f*(gx*gx + gy*gy);

        // rot_align = clip(trace(pr^T gr)/3, 0, 1)
        float dot = 0.0f;
        #pragma unroll
        for (int j = 0; j < 9; j++) dot += pr[j] * gr[j];
        float rot_align = fminf(fmaxf(dot * (1.0f / 3.0f), 0.0f), 1.0f);

        // extents: |R @ (d/2)|
        float pe[3], ge[3];
        #pragma unroll
        for (int i = 0; i < 3; i++) {
            pe[i] = 0.5f * fabsf(pr[3*i]*p[3] + pr[3*i+1]*p[4] + pr[3*i+2]*p[5]);
            ge[i] = 0.5f * fabsf(gr[3*i]*t[3] + gr[3*i+1]*t[4] + gr[3*i+2]*t[5]);
        }

        float prod = 1.0f;
        #pragma unroll
        for (int i = 0; i < 3; i++) {
            float cd  = fabsf(p[i] - t[i]);
            float num = fmaxf(2.0f * fminf(pe[i], ge[i]) - cd, 0.0f);
            prod *= num / (pe[i] + ge[i] + EPSF);
        }
        ov = fminf(fmaxf(prod * rot_align, 0.0f), 1.0f);
    }

    // ---- block reduction (warp shuffle + smem) ----
    #pragma unroll
    for (int off = 16; off > 0; off >>= 1) {
        l1_sum += __shfl_down_sync(0xFFFFFFFFu, l1_sum, off);
        ov     += __shfl_down_sync(0xFFFFFFFFu, ov, off);
    }
    __shared__ float warp_l1[THREADS / 32];
    __shared__ float warp_ov[THREADS / 32];
    const int lane = tid & 31;
    const int wid  = tid >> 5;
    if (lane == 0) { warp_l1[wid] = l1_sum; warp_ov[wid] = ov; }
    __syncthreads();
    if (wid == 0) {
        float a = (lane < THREADS / 32) ? warp_l1[lane] : 0.0f;
        float b = (lane < THREADS / 32) ? warp_ov[lane] : 0.0f;
        #pragma unroll
        for (int off = 4; off > 0; off >>= 1) {
            a += __shfl_down_sync(0xFFFFFFFFu, a, off);
            b += __shfl_down_sync(0xFFFFFFFFu, b, off);
        }
        if (lane == 0) {
            atomicAdd(&g_acc[0], (double)a);
            atomicAdd(&g_acc[1], (double)b);
        }
    }
}

__global__ void hl_final_kernel(float* __restrict__ out) {
    double param_loss = g_acc[0] / ((double)NROWS * 10.0);
    double mean_ov    = g_acc[1] / (double)NROWS;
    out[0] = (float)(param_loss + 0.5 * (1.0 - mean_ov));
}

extern "C" void kernel_launch(void* const* d_in, const int* in_sizes, int n_in,
                              void* d_out, int out_size) {
    const float* preds   = (const float*)d_in[0];
    const float* targets = (const float*)d_in[1];
    float* out = (float*)d_out;

    hl_init_kernel<<<1, 1>>>();
    hl_main_kernel<<<NBLOCKS, THREADS>>>(preds, targets);
    hl_final_kernel<<<1, 1>>>(out);
}